// round 1
// baseline (speedup 1.0000x reference)
#include <cuda_runtime.h>
#include <math.h>

// Problem constants
#define NB   256      // batch
#define NH   1024     // hidden
#define NP   3        // palette dim
#define NS   512      // encoder seq len
#define G3   3072     // 3*H
#define BN_EPS 1e-5f

// ---------------- scratch (no allocations allowed) ----------------
__device__ float g_gi[NB * G3];      // x @ Wih^T + bih
__device__ float g_gh[NB * G3];      // h0 @ Whh^T + bhh
__device__ float g_h [NB * NH];      // GRU output h
__device__ float g_q [NB * NH];      // raw attn query (pre-normalize)
__device__ float g_ctx[NB * NH];     // attention context
__device__ float g_y [NB * NH];      // relu(cat @ W1^T + b1)
__device__ float g_mu[NH];
__device__ float g_rstd[NH];

// Block-wide sum reduce + broadcast. Assumes blockDim.x == 256. sred has >= 9 floats.
__device__ __forceinline__ float block_reduce_sum_256(float v, float* sred) {
#pragma unroll
    for (int o = 16; o > 0; o >>= 1) v += __shfl_xor_sync(0xffffffffu, v, o);
    int w = threadIdx.x >> 5;
    int lane = threadIdx.x & 31;
    if (lane == 0) sred[w] = v;
    __syncthreads();
    if (w == 0) {
        float x = (lane < 8) ? sred[lane] : 0.f;
#pragma unroll
        for (int o = 4; o > 0; o >>= 1) x += __shfl_xor_sync(0xffffffffu, x, o);
        if (lane == 0) sred[8] = x;
    }
    __syncthreads();
    return sred[8];
}

// ---------------- generic tiled SGEMM: C[M,N] = A[M,K] @ W[N,K]^T + bias ----------------
// A is split into two row-major segments: k < split -> A0 (lda0), else A1 (lda1).
// M is always 256 (gridDim.y == 4). BM=BN=64, BK=8, 256 threads, 4x4 per thread.
__global__ __launch_bounds__(256) void sgemm64(
    const float* __restrict__ A0, int lda0,
    const float* __restrict__ A1, int lda1, int split,
    const float* __restrict__ W,
    const float* __restrict__ bias,
    float* __restrict__ C,
    int N, int K, int do_relu)
{
    __shared__ float As[8][64];
    __shared__ float Ws[8][64];
    const int tid = threadIdx.x;
    const int tx = tid & 15;          // 0..15 -> N
    const int ty = tid >> 4;          // 0..15 -> M
    const int row0 = blockIdx.y * 64;
    const int col0 = blockIdx.x * 64;

    float acc[4][4] = {};

    for (int kt = 0; kt < K; kt += 8) {
#pragma unroll
        for (int i = tid; i < 512; i += 256) {
            int r  = i >> 3;
            int kk = i & 7;
            int k  = kt + kk;
            float a = 0.f, wv = 0.f;
            if (k < K) {
                int row = row0 + r;
                a  = (k < split) ? A0[(size_t)row * lda0 + k]
                                 : A1[(size_t)row * lda1 + (k - split)];
                wv = W[(size_t)(col0 + r) * K + k];
            }
            As[kk][r] = a;
            Ws[kk][r] = wv;
        }
        __syncthreads();
#pragma unroll
        for (int kk = 0; kk < 8; kk++) {
            float4 av = *(const float4*)&As[kk][ty * 4];
            float4 wv = *(const float4*)&Ws[kk][tx * 4];
            float a[4] = {av.x, av.y, av.z, av.w};
            float w[4] = {wv.x, wv.y, wv.z, wv.w};
#pragma unroll
            for (int i = 0; i < 4; i++)
#pragma unroll
                for (int j = 0; j < 4; j++)
                    acc[i][j] = fmaf(a[i], w[j], acc[i][j]);
        }
        __syncthreads();
    }

#pragma unroll
    for (int i = 0; i < 4; i++) {
        int row = row0 + ty * 4 + i;
#pragma unroll
        for (int j = 0; j < 4; j++) {
            int col = col0 + tx * 4 + j;
            float v = acc[i][j] + bias[col];
            if (do_relu) v = fmaxf(v, 0.f);
            C[(size_t)row * N + col] = v;
        }
    }
}

// ---------------- GRU gate combine: h = (1-z)*n + z*h0 ----------------
__global__ __launch_bounds__(256) void gru_combine(
    const float* __restrict__ h0, float* __restrict__ h_out_global)
{
    int idx = blockIdx.x * 256 + threadIdx.x;   // over B*H
    int b = idx >> 10;
    int i = idx & 1023;
    const float* gi = g_gi + (size_t)b * G3;
    const float* gh = g_gh + (size_t)b * G3;
    float r = 1.f / (1.f + expf(-(gi[i]          + gh[i])));
    float z = 1.f / (1.f + expf(-(gi[NH + i]     + gh[NH + i])));
    float n = tanhf(gi[2 * NH + i] + r * gh[2 * NH + i]);
    float hv = (1.f - z) * n + z * h0[idx];
    g_h[idx] = hv;
    h_out_global[idx] = hv;
}

// ---------------- fused attention (flash-style single pass over S) ----------------
// One block per batch row b. 256 threads, each owns 4 hidden elems (float4).
// - normalizes q_b in-register
// - online softmax with running context accumulator (reads encoder_outputs ONCE)
// - caches energies in smem to emit attn_weights exactly (masked -> 0)
__global__ __launch_bounds__(256) void attn_flash(
    const float* __restrict__ E,        // [S, B, H]
    const int*   __restrict__ lens,     // [B]
    float* __restrict__ ctx_out,        // d_out context section [B, H]
    float* __restrict__ attn_out)       // d_out attn section [B, S]
{
    const int b = blockIdx.x;
    const int tid = threadIdx.x;
    __shared__ float se[NS];
    __shared__ float sred[9];

    // load + L2-normalize the query row (held in registers)
    float4 qv = ((const float4*)(g_q + (size_t)b * NH))[tid];
    float ss = qv.x * qv.x + qv.y * qv.y + qv.z * qv.z + qv.w * qv.w;
    float tot = block_reduce_sum_256(ss, sred);
    float inv = 1.f / sqrtf(tot);
    qv.x *= inv; qv.y *= inv; qv.z *= inv; qv.w *= inv;

    const int len = lens[b];
    const float4* E4 = (const float4*)E;
    const size_t base = (size_t)b * (NH / 4) + tid;
    const size_t sstride = (size_t)NB * (NH / 4);   // float4 stride per s

    float m = -INFINITY, l = 0.f;
    float4 c = {0.f, 0.f, 0.f, 0.f};

    // depth-4 prefetch ring (statically indexed => registers)
    float4 buf[4];
#pragma unroll
    for (int u = 0; u < 4; u++)
        if (u < len) buf[u] = E4[base + (size_t)u * sstride];

    for (int s0 = 0; s0 < len; s0 += 4) {
#pragma unroll
        for (int u = 0; u < 4; u++) {
            int s = s0 + u;
            if (s >= len) break;             // uniform across block
            float4 v = buf[u];
            int sp = s + 4;
            if (sp < len) buf[u] = E4[base + (size_t)sp * sstride];

            float part = v.x * qv.x + v.y * qv.y + v.z * qv.z + v.w * qv.w;
            float e = block_reduce_sum_256(part, sred);
            if (tid == 0) se[s] = e;

            float mn = fmaxf(m, e);
            float sc = expf(m - mn);         // expf(-inf)=0 handles first iter
            float p  = expf(e - mn);
            l = l * sc + p;
            c.x = c.x * sc + p * v.x;
            c.y = c.y * sc + p * v.y;
            c.z = c.z * sc + p * v.z;
            c.w = c.w * sc + p * v.w;
            m = mn;
        }
    }

    const float linv = 1.f / l;
    float4 cv = {c.x * linv, c.y * linv, c.z * linv, c.w * linv};
    ((float4*)(g_ctx + (size_t)b * NH))[tid] = cv;
    ((float4*)ctx_out)[(size_t)b * (NH / 4) + tid] = cv;

    __syncthreads();   // se[] visible to all
    for (int s = tid; s < NS; s += 256) {
        float w = (s < len) ? expf(se[s] - m) * linv : 0.f;
        attn_out[(size_t)b * NS + s] = w;
    }
}

// ---------------- BatchNorm batch stats (per column over B=256 rows) ----------------
__global__ __launch_bounds__(256) void bn_stats()
{
    int h = blockIdx.x;
    int b = threadIdx.x;
    __shared__ float sred[9];
    float v = g_y[(size_t)b * NH + h];
    float s = block_reduce_sum_256(v, sred);
    float mu = s * (1.f / 256.f);
    float d = v - mu;
    float vs = block_reduce_sum_256(d * d, sred);
    if (b == 0) {
        g_mu[h] = mu;
        g_rstd[h] = rsqrtf(vs * (1.f / 256.f) + BN_EPS);
    }
}

// ---------------- final: out[b,p] = sum_h BN(y)[b,h] * W2[p,h] + b2[p] ----------------
__global__ __launch_bounds__(96) void out_final(
    const float* __restrict__ W2, const float* __restrict__ b2,
    const float* __restrict__ gamma, const float* __restrict__ beta,
    float* __restrict__ out)
{
    int b = blockIdx.x;
    int w = threadIdx.x >> 5;     // 0..2
    int lane = threadIdx.x & 31;
    float sum = 0.f;
    for (int h = lane; h < NH; h += 32) {
        float yb = gamma[h] * (g_y[(size_t)b * NH + h] - g_mu[h]) * g_rstd[h] + beta[h];
        sum = fmaf(yb, W2[(size_t)w * NH + h], sum);
    }
#pragma unroll
    for (int o = 16; o > 0; o >>= 1) sum += __shfl_xor_sync(0xffffffffu, sum, o);
    if (lane == 0) out[b * NP + w] = sum + b2[w];
}

// ---------------- launch ----------------
extern "C" void kernel_launch(void* const* d_in, const int* in_sizes, int n_in,
                              void* d_out, int out_size)
{
    const float* palette      = (const float*)d_in[0];   // [1,B,P]
    const float* last_context = (const float*)d_in[1];   // [1,B,H]
    const float* last_hidden  = (const float*)d_in[2];   // [1,B,H]
    const float* enc          = (const float*)d_in[3];   // [S,B,H]
    const int*   lens         = (const int*)  d_in[4];   // [B]
    // d_in[5] = signal (unused)
    const float* attn_W = (const float*)d_in[6];
    const float* attn_b = (const float*)d_in[7];
    const float* Wih    = (const float*)d_in[8];    // [3H, H+P]
    const float* Whh    = (const float*)d_in[9];    // [3H, H]
    const float* bih    = (const float*)d_in[10];
    const float* bhh    = (const float*)d_in[11];
    const float* W1     = (const float*)d_in[12];   // [H, 2H]
    const float* b1     = (const float*)d_in[13];
    const float* gamma  = (const float*)d_in[14];
    const float* beta   = (const float*)d_in[15];
    const float* W2     = (const float*)d_in[16];   // [P, H]
    const float* b2     = (const float*)d_in[17];

    float* out      = (float*)d_out;                // [B,3]       = 768
    float* out_ctx  = out + NB * NP;                // [1,B,H]     = 262144
    float* out_h    = out_ctx + NB * NH;            // [1,B,H]     = 262144
    float* out_attn = out_h + NB * NH;              // [B,1,S]     = 131072

    float *p_gi, *p_gh, *p_h, *p_q, *p_ctx, *p_y;
    cudaGetSymbolAddress((void**)&p_gi,  g_gi);
    cudaGetSymbolAddress((void**)&p_gh,  g_gh);
    cudaGetSymbolAddress((void**)&p_h,   g_h);
    cudaGetSymbolAddress((void**)&p_q,   g_q);
    cudaGetSymbolAddress((void**)&p_ctx, g_ctx);
    cudaGetSymbolAddress((void**)&p_y,   g_y);

    // 1) gi = [palette | last_context] @ Wih^T + bih   (K = 1027)
    sgemm64<<<dim3(G3 / 64, NB / 64), 256>>>(
        palette, NP, last_context, NH, NP, Wih, bih, p_gi, G3, NH + NP, 0);
    // 2) gh = h0 @ Whh^T + bhh                          (K = 1024)
    sgemm64<<<dim3(G3 / 64, NB / 64), 256>>>(
        last_hidden, NH, last_hidden, NH, NH, Whh, bhh, p_gh, G3, NH, 0);
    // 3) GRU combine -> h (scratch + d_out)
    gru_combine<<<(NB * NH) / 256, 256>>>(last_hidden, out_h);
    // 4) q_raw = h @ attn_W^T + attn_b
    sgemm64<<<dim3(NH / 64, NB / 64), 256>>>(
        p_h, NH, p_h, NH, NH, attn_W, attn_b, p_q, NH, NH, 0);
    // 5) fused normalize + masked flash softmax attention + context + weights
    attn_flash<<<NB, 256>>>(enc, lens, out_ctx, out_attn);
    // 6) y = relu([h | ctx] @ W1^T + b1)               (K = 2048)
    sgemm64<<<dim3(NH / 64, NB / 64), 256>>>(
        p_h, NH, p_ctx, NH, NH, W1, b1, p_y, NH, 2 * NH, 1);
    // 7) BN batch stats
    bn_stats<<<NH, 256>>>();
    // 8) out = BN(y) @ W2^T + b2
    out_final<<<NB, 96>>>(W2, b2, gamma, beta, out);
}

// round 2
// speedup vs baseline: 2.8107x; 2.8107x over previous
#include <cuda_runtime.h>
#include <math.h>

#define NB   256      // batch
#define NH   1024     // hidden
#define NP   3        // palette dim
#define NS   512      // encoder seq len
#define G3   3072     // 3*H
#define BN_EPS 1e-5f

// ---------------- scratch ----------------
__device__ float g_gi[NB * G3];
__device__ float g_gh[NB * G3];
__device__ float g_h [NB * NH];
__device__ float g_q [NB * NH];      // q partial (k 0..511)
__device__ float g_q2[NB * NH];      // q partial (k 512..1023)
__device__ float g_ctx[NB * NH];
__device__ float g_y [NB * NH];      // y partial (h part) -> combined y after bn kernel
__device__ float g_y2[NB * NH];      // y partial (ctx part)
__device__ float g_mu[NH];
__device__ float g_rstd[NH];

// ---------------- packed fp32x2 FMA (Blackwell FFMA2) ----------------
__device__ __forceinline__ void fma2(unsigned long long& d,
                                     unsigned long long a,
                                     unsigned long long b) {
    asm("fma.rn.f32x2 %0, %1, %2, %0;" : "+l"(d) : "l"(a), "l"(b));
}
__device__ __forceinline__ float hsum2(unsigned long long v) {
    unsigned lo = (unsigned)(v & 0xffffffffull);
    unsigned hi = (unsigned)(v >> 32);
    return __uint_as_float(lo) + __uint_as_float(hi);
}

// ---------------- GEMM (C[M,N] = A[M,K] @ W[N,K]^T), f32x2 pipeline ----------------
// 64x64 tile, BK=16, 128 threads, per-thread 4(M) x 8(N).
// Pairing along K: each acc holds (even-k sum, odd-k sum); horizontal add at the end.
struct GArg {
    const float* A;      // [256, lda]
    int lda;
    const float* W;      // rows of length ldw; element W[n*ldw + kOff + k]
    int ldw;
    int kOff;
    const float* bias;   // nullable, length N
    const float* extra;  // nullable: rank-extraK update, extra[m*extraK+p] * W[n*ldw+p]
    int extraK;
    float* C;
    int ldc;
};

#define SMP 20           // padded smem row stride (floats): conflict-free & 16B aligned

__global__ __launch_bounds__(128, 3) void gemm_f32x2(GArg ga, GArg gb, int K)
{
    const GArg g = blockIdx.z ? gb : ga;
    __shared__ __align__(16) float As[2][64 * SMP];
    __shared__ __align__(16) float Ws[2][64 * SMP];

    const int tid = threadIdx.x;
    const int tx  = tid & 7;          // N group: cols tx + 8j
    const int ty  = tid >> 3;         // M group: rows ty + 16i
    const int row0 = blockIdx.y * 64;
    const int col0 = blockIdx.x * 64;
    const bool walign = ((g.ldw & 3) == 0) && ((g.kOff & 3) == 0);

    unsigned long long acc[4][8];
#pragma unroll
    for (int i = 0; i < 4; i++)
#pragma unroll
        for (int j = 0; j < 8; j++) acc[i][j] = 0ull;   // (+0.f, +0.f)

    const int nt = K >> 4;
    float4 ra[2], rwa[2];
    float  rws[8];

    // ---- tile load helpers (inlined) ----
    // A tile: 64 rows x 16 k  -> 2 float4 per thread
#define LOAD_A(KT)                                                          \
    {                                                                       \
        _Pragma("unroll")                                                   \
        for (int l = 0; l < 2; l++) {                                       \
            int idx = tid + l * 128;                                        \
            int r = idx >> 2, kq = idx & 3;                                 \
            ra[l] = *(const float4*)&g.A[(size_t)(row0 + r) * g.lda + (KT) + kq * 4]; \
        }                                                                   \
    }
#define STS_A(BUF)                                                          \
    {                                                                       \
        _Pragma("unroll")                                                   \
        for (int l = 0; l < 2; l++) {                                       \
            int idx = tid + l * 128;                                        \
            int r = idx >> 2, kq = idx & 3;                                 \
            *(float4*)&As[BUF][r * SMP + kq * 4] = ra[l];                   \
        }                                                                   \
    }
#define LOAD_W(KT)                                                          \
    {                                                                       \
        if (walign) {                                                       \
            _Pragma("unroll")                                               \
            for (int l = 0; l < 2; l++) {                                   \
                int idx = tid + l * 128;                                    \
                int r = idx >> 2, kq = idx & 3;                             \
                rwa[l] = *(const float4*)&g.W[(size_t)(col0 + r) * g.ldw + g.kOff + (KT) + kq * 4]; \
            }                                                               \
        } else {                                                            \
            _Pragma("unroll")                                               \
            for (int l = 0; l < 8; l++) {                                   \
                int idx = tid + l * 128;                                    \
                int r = idx >> 4, kk = idx & 15;                            \
                rws[l] = g.W[(size_t)(col0 + r) * g.ldw + g.kOff + (KT) + kk]; \
            }                                                               \
        }                                                                   \
    }
#define STS_W(BUF)                                                          \
    {                                                                       \
        if (walign) {                                                       \
            _Pragma("unroll")                                               \
            for (int l = 0; l < 2; l++) {                                   \
                int idx = tid + l * 128;                                    \
                int r = idx >> 2, kq = idx & 3;                             \
                *(float4*)&Ws[BUF][r * SMP + kq * 4] = rwa[l];              \
            }                                                               \
        } else {                                                            \
            _Pragma("unroll")                                               \
            for (int l = 0; l < 8; l++) {                                   \
                int idx = tid + l * 128;                                    \
                int r = idx >> 4, kk = idx & 15;                            \
                Ws[BUF][r * SMP + kk] = rws[l];                             \
            }                                                               \
        }                                                                   \
    }

    LOAD_A(0); LOAD_W(0);
    STS_A(0);  STS_W(0);
    __syncthreads();

    for (int t = 0; t < nt; t++) {
        const int buf = t & 1;
        if (t + 1 < nt) { LOAD_A((t + 1) << 4); LOAD_W((t + 1) << 4); }

        // compute on buf
#pragma unroll
        for (int kq = 0; kq < 4; kq++) {
            ulonglong2 av[4], bv[8];
#pragma unroll
            for (int i = 0; i < 4; i++)
                av[i] = *(const ulonglong2*)&As[buf][(ty + 16 * i) * SMP + kq * 4];
#pragma unroll
            for (int j = 0; j < 8; j++)
                bv[j] = *(const ulonglong2*)&Ws[buf][(tx + 8 * j) * SMP + kq * 4];
#pragma unroll
            for (int i = 0; i < 4; i++)
#pragma unroll
                for (int j = 0; j < 8; j++) {
                    fma2(acc[i][j], av[i].x, bv[j].x);
                    fma2(acc[i][j], av[i].y, bv[j].y);
                }
        }

        if (t + 1 < nt) {
            const int nb = (t + 1) & 1;
            STS_A(nb); STS_W(nb);
            __syncthreads();
        }
    }

    // epilogue
#pragma unroll
    for (int i = 0; i < 4; i++) {
        const int m = row0 + ty + 16 * i;
#pragma unroll
        for (int j = 0; j < 8; j++) {
            const int n = col0 + tx + 8 * j;
            float v = hsum2(acc[i][j]);
            if (g.bias) v += g.bias[n];
            if (g.extraK) {
                for (int p = 0; p < g.extraK; p++)
                    v += g.extra[(size_t)m * g.extraK + p] * g.W[(size_t)n * g.ldw + p];
            }
            g.C[(size_t)m * g.ldc + n] = v;
        }
    }
#undef LOAD_A
#undef STS_A
#undef LOAD_W
#undef STS_W
}

// ---------------- GRU gate combine ----------------
__global__ __launch_bounds__(256) void gru_combine(
    const float* __restrict__ h0, float* __restrict__ h_out_global)
{
    int idx = blockIdx.x * 256 + threadIdx.x;   // over B*H
    int b = idx >> 10;
    int i = idx & 1023;
    const float* gi = g_gi + (size_t)b * G3;
    const float* gh = g_gh + (size_t)b * G3;
    float r = 1.f / (1.f + expf(-(gi[i]          + gh[i])));
    float z = 1.f / (1.f + expf(-(gi[NH + i]     + gh[NH + i])));
    float n = tanhf(gi[2 * NH + i] + r * gh[2 * NH + i]);
    float hv = (1.f - z) * n + z * h0[idx];
    g_h[idx] = hv;
    h_out_global[idx] = hv;
}

// ---------------- fused attention (flash-style, 4 energies per reduce round) ----------------
__global__ __launch_bounds__(256) void attn_flash(
    const float* __restrict__ E,        // [S, B, H]
    const int*   __restrict__ lens,     // [B]
    const float* __restrict__ attn_b,   // [H]
    float* __restrict__ ctx_out,        // [B, H]
    float* __restrict__ attn_out)       // [B, S]
{
    const int b = blockIdx.x;
    const int tid = threadIdx.x;
    const int warp = tid >> 5, lane = tid & 31;
    __shared__ float se[NS];
    __shared__ float sred2[8][4];
    __shared__ float e4[4];
    __shared__ float snorm[9];

    // q = q1 + q2 + bias, then L2-normalize (held in registers, float4/thread)
    float4 q1 = ((const float4*)(g_q  + (size_t)b * NH))[tid];
    float4 q2 = ((const float4*)(g_q2 + (size_t)b * NH))[tid];
    float4 bb = ((const float4*)attn_b)[tid];
    float4 qv = {q1.x + q2.x + bb.x, q1.y + q2.y + bb.y,
                 q1.z + q2.z + bb.z, q1.w + q2.w + bb.w};
    {
        float ss = qv.x * qv.x + qv.y * qv.y + qv.z * qv.z + qv.w * qv.w;
#pragma unroll
        for (int o = 16; o > 0; o >>= 1) ss += __shfl_xor_sync(0xffffffffu, ss, o);
        if (lane == 0) snorm[warp] = ss;
        __syncthreads();
        if (warp == 0) {
            float x = (lane < 8) ? snorm[lane] : 0.f;
#pragma unroll
            for (int o = 4; o > 0; o >>= 1) x += __shfl_xor_sync(0xffffffffu, x, o);
            if (lane == 0) snorm[8] = x;
        }
        __syncthreads();
        float inv = rsqrtf(snorm[8]);
        qv.x *= inv; qv.y *= inv; qv.z *= inv; qv.w *= inv;
    }

    const int len = lens[b];
    const float4* E4 = (const float4*)E;
    const size_t base = (size_t)b * (NH / 4) + tid;
    const size_t sstride = (size_t)NB * (NH / 4);

    float m = -1e30f, l = 0.f;
    float4 c = {0.f, 0.f, 0.f, 0.f};

    float4 buf[4];
#pragma unroll
    for (int u = 0; u < 4; u++)
        if (u < len) buf[u] = E4[base + (size_t)u * sstride];

    for (int s0 = 0; s0 < len; s0 += 4) {
        float4 v[4];
        float p[4];
#pragma unroll
        for (int u = 0; u < 4; u++) {
            v[u] = buf[u];
            int sp = s0 + 4 + u;
            if (sp < len) buf[u] = E4[base + (size_t)sp * sstride];
            p[u] = (s0 + u < len)
                 ? (v[u].x * qv.x + v[u].y * qv.y + v[u].z * qv.z + v[u].w * qv.w)
                 : 0.f;
        }
        // 4 simultaneous block reductions
#pragma unroll
        for (int u = 0; u < 4; u++)
#pragma unroll
            for (int o = 16; o > 0; o >>= 1)
                p[u] += __shfl_xor_sync(0xffffffffu, p[u], o);
        if (lane == 0) {
#pragma unroll
            for (int u = 0; u < 4; u++) sred2[warp][u] = p[u];
        }
        __syncthreads();
        if (warp == 0) {
            int w = lane & 7, u = lane >> 3;
            float x = sred2[w][u];
            x += __shfl_xor_sync(0xffffffffu, x, 4);
            x += __shfl_xor_sync(0xffffffffu, x, 2);
            x += __shfl_xor_sync(0xffffffffu, x, 1);
            if (w == 0) {
                e4[u] = x;
                if (s0 + u < len) se[s0 + u] = x;
            }
        }
        __syncthreads();

#pragma unroll
        for (int u = 0; u < 4; u++) {
            if (s0 + u < len) {
                float e  = e4[u];
                float mn = fmaxf(m, e);
                float sc = __expf(m - mn);
                float pu = __expf(e - mn);
                l = l * sc + pu;
                c.x = c.x * sc + pu * v[u].x;
                c.y = c.y * sc + pu * v[u].y;
                c.z = c.z * sc + pu * v[u].z;
                c.w = c.w * sc + pu * v[u].w;
                m = mn;
            }
        }
        __syncthreads();   // protect e4/sred2 reuse next round
    }

    const float linv = 1.f / l;
    float4 cv = {c.x * linv, c.y * linv, c.z * linv, c.w * linv};
    ((float4*)(g_ctx + (size_t)b * NH))[tid] = cv;
    ((float4*)ctx_out)[(size_t)b * (NH / 4) + tid] = cv;

    for (int s = tid; s < NS; s += 256) {
        float w = (s < len) ? __expf(se[s] - m) * linv : 0.f;
        attn_out[(size_t)b * NS + s] = w;
    }
}

// ---------------- BN: combine y partials + bias + relu, batch stats ----------------
__global__ __launch_bounds__(256) void bn_relu_stats(const float* __restrict__ b1)
{
    int h = blockIdx.x;
    int b = threadIdx.x;
    __shared__ float sred[9];
    int warp = b >> 5, lane = b & 31;

    float v = g_y[(size_t)b * NH + h] + g_y2[(size_t)b * NH + h] + b1[h];
    v = fmaxf(v, 0.f);
    g_y[(size_t)b * NH + h] = v;

    float s = v;
#pragma unroll
    for (int o = 16; o > 0; o >>= 1) s += __shfl_xor_sync(0xffffffffu, s, o);
    if (lane == 0) sred[warp] = s;
    __syncthreads();
    if (warp == 0) {
        float x = (lane < 8) ? sred[lane] : 0.f;
#pragma unroll
        for (int o = 4; o > 0; o >>= 1) x += __shfl_xor_sync(0xffffffffu, x, o);
        if (lane == 0) sred[8] = x;
    }
    __syncthreads();
    float mu = sred[8] * (1.f / 256.f);

    float d = v - mu;
    float vs = d * d;
#pragma unroll
    for (int o = 16; o > 0; o >>= 1) vs += __shfl_xor_sync(0xffffffffu, vs, o);
    if (lane == 0) sred[warp] = vs;
    __syncthreads();
    if (warp == 0) {
        float x = (lane < 8) ? sred[lane] : 0.f;
#pragma unroll
        for (int o = 4; o > 0; o >>= 1) x += __shfl_xor_sync(0xffffffffu, x, o);
        if (lane == 0) sred[8] = x;
    }
    __syncthreads();
    if (b == 0) {
        g_mu[h] = mu;
        g_rstd[h] = rsqrtf(sred[8] * (1.f / 256.f) + BN_EPS);
    }
}

// ---------------- final: out[b,p] = BN(y)[b,:] . W2[p,:] + b2[p] ----------------
__global__ __launch_bounds__(96) void out_final(
    const float* __restrict__ W2, const float* __restrict__ b2,
    const float* __restrict__ gamma, const float* __restrict__ beta,
    float* __restrict__ out)
{
    int b = blockIdx.x;
    int w = threadIdx.x >> 5;
    int lane = threadIdx.x & 31;
    float sum = 0.f;
    for (int h = lane; h < NH; h += 32) {
        float yb = gamma[h] * (g_y[(size_t)b * NH + h] - g_mu[h]) * g_rstd[h] + beta[h];
        sum = fmaf(yb, W2[(size_t)w * NH + h], sum);
    }
#pragma unroll
    for (int o = 16; o > 0; o >>= 1) sum += __shfl_xor_sync(0xffffffffu, sum, o);
    if (lane == 0) out[b * NP + w] = sum + b2[w];
}

// ---------------- launch ----------------
extern "C" void kernel_launch(void* const* d_in, const int* in_sizes, int n_in,
                              void* d_out, int out_size)
{
    const float* palette      = (const float*)d_in[0];
    const float* last_context = (const float*)d_in[1];
    const float* last_hidden  = (const float*)d_in[2];
    const float* enc          = (const float*)d_in[3];
    const int*   lens         = (const int*)  d_in[4];
    const float* attn_W = (const float*)d_in[6];
    const float* attn_b = (const float*)d_in[7];
    const float* Wih    = (const float*)d_in[8];
    const float* Whh    = (const float*)d_in[9];
    const float* bih    = (const float*)d_in[10];
    const float* bhh    = (const float*)d_in[11];
    const float* W1     = (const float*)d_in[12];
    const float* b1     = (const float*)d_in[13];
    const float* gamma  = (const float*)d_in[14];
    const float* beta   = (const float*)d_in[15];
    const float* W2     = (const float*)d_in[16];
    const float* b2     = (const float*)d_in[17];

    float* out      = (float*)d_out;
    float* out_ctx  = out + NB * NP;
    float* out_h    = out_ctx + NB * NH;
    float* out_attn = out_h + NB * NH;

    float *p_gi, *p_gh, *p_h, *p_q, *p_q2, *p_ctx, *p_y, *p_y2;
    cudaGetSymbolAddress((void**)&p_gi,  g_gi);
    cudaGetSymbolAddress((void**)&p_gh,  g_gh);
    cudaGetSymbolAddress((void**)&p_h,   g_h);
    cudaGetSymbolAddress((void**)&p_q,   g_q);
    cudaGetSymbolAddress((void**)&p_q2,  g_q2);
    cudaGetSymbolAddress((void**)&p_ctx, g_ctx);
    cudaGetSymbolAddress((void**)&p_y,   g_y);
    cudaGetSymbolAddress((void**)&p_y2,  g_y2);

    // 1) gi (z=0) + gh (z=1), K=1024
    {
        GArg a = {last_context, NH, Wih, NH + NP, NP, bih, palette, NP, p_gi, G3};
        GArg b = {last_hidden,  NH, Whh, NH,      0,  bhh, nullptr, 0,  p_gh, G3};
        gemm_f32x2<<<dim3(G3 / 64, NB / 64, 2), 128>>>(a, b, NH);
    }
    // 2) GRU combine -> h
    gru_combine<<<(NB * NH) / 256, 256>>>(last_hidden, out_h);
    // 3) q split-K2: z=0 k[0,512), z=1 k[512,1024)
    {
        GArg a = {p_h,       NH, attn_W, NH, 0,   nullptr, nullptr, 0, p_q,  NH};
        GArg b = {p_h + 512, NH, attn_W, NH, 512, nullptr, nullptr, 0, p_q2, NH};
        gemm_f32x2<<<dim3(NH / 64, NB / 64, 2), 128>>>(a, b, 512);
    }
    // 4) attention (adds q partials + bias, normalizes, flash softmax, context, weights)
    attn_flash<<<NB, 256>>>(enc, lens, attn_b, out_ctx, out_attn);
    // 5) y split: z=0 h-part, z=1 ctx-part (bias/relu deferred to BN kernel)
    {
        GArg a = {p_h,   NH, W1, 2 * NH, 0,    nullptr, nullptr, 0, p_y,  NH};
        GArg b = {p_ctx, NH, W1, 2 * NH, 1024, nullptr, nullptr, 0, p_y2, NH};
        gemm_f32x2<<<dim3(NH / 64, NB / 64, 2), 128>>>(a, b, NH);
    }
    // 6) combine + relu + BN stats
    bn_relu_stats<<<NH, 256>>>(b1);
    // 7) final projection
    out_final<<<NB, 96>>>(W2, b2, gamma, beta, out);
}